// round 10
// baseline (speedup 1.0000x reference)
#include <cuda_runtime.h>

#define DIMS 2048
#define SEQ  4096
#define SENT 2.0f   // sentinel: tanh output is in (-1,1), h0 = 0 -> never 2.0

// ---------------- scratch (static device globals; no allocation) ------------
__device__ float g_A[SEQ * DIMS];                         // A = X @ W_hi^T + b
__device__ __align__(16) float g_hist[(SEQ + 1) * DIMS];  // write-once h history

// ---------------- small asm helpers -----------------------------------------
__device__ __forceinline__ float tanh_fast(float x) {
    float y;
    asm("tanh.approx.f32 %0, %1;" : "=f"(y) : "f"(x));
    return y;
}
__device__ __forceinline__ float4 ldg_vol_v4(const float4* p) {
    float4 v;
    asm volatile("ld.volatile.global.v4.f32 {%0,%1,%2,%3}, [%4];"
                 : "=f"(v.x), "=f"(v.y), "=f"(v.z), "=f"(v.w) : "l"(p));
    return v;
}
__device__ __forceinline__ void stg_vol_v4(float4* p, float4 v) {
    asm volatile("st.volatile.global.v4.f32 [%0], {%1,%2,%3,%4};"
                 :: "l"(p), "f"(v.x), "f"(v.y), "f"(v.z), "f"(v.w) : "memory");
}
// packed fp32x2 ops
__device__ __forceinline__ void ffma2(unsigned long long& d,
                                      unsigned long long a, unsigned long long b) {
    asm("fma.rn.f32x2 %0, %1, %2, %0;" : "+l"(d) : "l"(a), "l"(b));
}
__device__ __forceinline__ unsigned long long add2(unsigned long long a,
                                                   unsigned long long b) {
    unsigned long long s;
    asm("add.rn.f32x2 %0, %1, %2;" : "=l"(s) : "l"(a), "l"(b));
    return s;
}
__device__ __forceinline__ unsigned long long pack2(float x) {
    unsigned long long r;
    asm("mov.b64 %0, {%1, %1};" : "=l"(r) : "f"(x));
    return r;
}
__device__ __forceinline__ float f32x2_hsum(unsigned long long a, unsigned long long b) {
    unsigned long long s = add2(a, b);
    float2 f = *reinterpret_cast<float2*>(&s);
    return f.x + f.y;
}

// ---------------- init: poison history, seed h0 -------------------------------
__global__ void poison_kernel() {
    const float4 s = make_float4(SENT, SENT, SENT, SENT);
    float4* p = (float4*)g_hist;
    const int total = (SEQ + 1) * (DIMS / 4);
    for (int w = blockIdx.x * blockDim.x + threadIdx.x; w < total;
         w += gridDim.x * blockDim.x)
        p[w] = s;
}
__global__ void seed_kernel(const float* __restrict__ h0) {
    int i = blockIdx.x * blockDim.x + threadIdx.x;
    if (i < DIMS) g_hist[i] = h0[i];
}

// ---------------- phase 1: A = X @ W^T + b  (packed f32x2 GEMM, R5 version) ---
#define BM 128
#define BN 128
#define BK 8

__global__ __launch_bounds__(256) void gemm_kernel(
    const float* __restrict__ X, const float* __restrict__ W,
    const float* __restrict__ b, float* __restrict__ A)
{
    __shared__ __align__(16) float Xs[BK][BM];
    __shared__ __align__(16) float Ws[BK][BN];

    const int tid = threadIdx.x;
    const int m0  = blockIdx.y * BM;
    const int n0  = blockIdx.x * BN;
    const int tx  = tid & 15;
    const int ty  = tid >> 4;
    const int lr  = tid >> 1;
    const int lk  = (tid & 1) * 4;

    unsigned long long acc[8][4];
#pragma unroll
    for (int i = 0; i < 8; i++)
#pragma unroll
        for (int jp = 0; jp < 4; jp++) acc[i][jp] = 0ull;

    for (int k0 = 0; k0 < DIMS; k0 += BK) {
        float4 xv = *(const float4*)(X + (size_t)(m0 + lr) * DIMS + k0 + lk);
        float4 wv = *(const float4*)(W + (size_t)(n0 + lr) * DIMS + k0 + lk);
        __syncthreads();
        Xs[lk + 0][lr] = xv.x; Xs[lk + 1][lr] = xv.y;
        Xs[lk + 2][lr] = xv.z; Xs[lk + 3][lr] = xv.w;
        Ws[lk + 0][lr] = wv.x; Ws[lk + 1][lr] = wv.y;
        Ws[lk + 2][lr] = wv.z; Ws[lk + 3][lr] = wv.w;
        __syncthreads();
#pragma unroll
        for (int k = 0; k < BK; k++) {
            unsigned long long xd[8], wp[4];
#pragma unroll
            for (int i = 0; i < 8; i++) xd[i] = pack2(Xs[k][ty + 16 * i]);
#pragma unroll
            for (int jp = 0; jp < 4; jp++)
                wp[jp] = *(const unsigned long long*)&Ws[k][tx * 2 + 32 * jp];
#pragma unroll
            for (int i = 0; i < 8; i++)
#pragma unroll
                for (int jp = 0; jp < 4; jp++) ffma2(acc[i][jp], xd[i], wp[jp]);
        }
    }
    unsigned long long bp[4];
#pragma unroll
    for (int jp = 0; jp < 4; jp++)
        bp[jp] = *(const unsigned long long*)&b[n0 + tx * 2 + 32 * jp];
#pragma unroll
    for (int i = 0; i < 8; i++) {
        const int m = m0 + ty + 16 * i;
#pragma unroll
        for (int jp = 0; jp < 4; jp++) {
            *(unsigned long long*)&A[(size_t)m * DIMS + n0 + tx * 2 + 32 * jp] =
                add2(acc[i][jp], bp[jp]);
        }
    }
}

// ---------------- phase 2: persistent sequential RNN --------------------------
// Champion (R5) structure with three reorderings:
//  (1) publish by WARP 7 (hi-wid arbiter priority -> publish STGs beat the
//      post-bar poll flood into the L1tex queue),
//  (2) residual out STGs moved after bar B (publish enters an empty queue),
//  (3) merged va/vb poll loop (overlapped discovery).
#define NCTA 128
#define RPC  16
#define RNN_THREADS 256

__global__ __launch_bounds__(RNN_THREADS, 1) void rnn_kernel(
    const float* __restrict__ X, const float* __restrict__ Whh,
    float* __restrict__ out)
{
    __shared__ __align__(16) float4 h_s[DIMS / 4];  // 8 KB
    __shared__ __align__(16) float  c_s[RPC];       // this CTA's 16 new h

    const int tid  = threadIdx.x;
    const int wid  = tid >> 5;
    const int lane = tid & 31;
    const int cta  = blockIdx.x;
    const int row0 = cta * RPC + wid * 2;
    const int row1 = row0 + 1;

    // W_hh slice in registers as packed f32x2 pairs (2 rows per warp).
    ulonglong2 w0[16], w1[16];
    {
        const ulonglong2* W0 = (const ulonglong2*)(Whh + (size_t)row0 * DIMS);
        const ulonglong2* W1 = (const ulonglong2*)(Whh + (size_t)row1 * DIMS);
#pragma unroll
        for (int k = 0; k < 16; k++) {
            w0[k] = W0[lane + 32 * k];
            w1[k] = W1[lane + 32 * k];
        }
    }

    for (int t = 0; t < SEQ; t++) {
        const float4* hb = (const float4*)(g_hist + (size_t)t * DIMS);
        float4*       hn = (float4*)(g_hist + (size_t)(t + 1) * DIMS);

        // Step-constant operands, off the h critical chain.
        float a0 = 0.f, a1 = 0.f, xr0 = 0.f, xr1 = 0.f;
        if (lane == 0) {
            a0  = g_A[(size_t)t * DIMS + row0];
            a1  = g_A[(size_t)t * DIMS + row1];
            xr0 = X[(size_t)t * DIMS + row0];
            xr1 = X[(size_t)t * DIMS + row1];
        }

        // Ingest h_prev: each thread owns 2 of the 512 16B words; payload IS
        // the signal. Merged loop: both words re-polled concurrently.
        {
            float4 va = ldg_vol_v4(hb + tid);
            float4 vb = ldg_vol_v4(hb + tid + RNN_THREADS);
            bool na = (va.x == SENT || va.y == SENT || va.z == SENT || va.w == SENT);
            bool nb = (vb.x == SENT || vb.y == SENT || vb.z == SENT || vb.w == SENT);
            while (na || nb) {
                if (na) va = ldg_vol_v4(hb + tid);
                if (nb) vb = ldg_vol_v4(hb + tid + RNN_THREADS);
                na = (va.x == SENT || va.y == SENT || va.z == SENT || va.w == SENT);
                nb = (vb.x == SENT || vb.y == SENT || vb.z == SENT || vb.w == SENT);
            }
            h_s[tid]               = va;
            h_s[tid + RNN_THREADS] = vb;
        }
        __syncthreads();   // bar A: h_s fully staged

        // 2 dot products per warp; W in registers, h broadcast from smem,
        // packed f32x2 FMA (2 MACs / instruction).
        unsigned long long a0x = 0ull, a0y = 0ull, a1x = 0ull, a1y = 0ull;
#pragma unroll
        for (int k = 0; k < 16; k++) {
            ulonglong2 hv = *(const ulonglong2*)&h_s[lane + 32 * k];
            ffma2(a0x, w0[k].x, hv.x);  ffma2(a0y, w0[k].y, hv.y);
            ffma2(a1x, w1[k].x, hv.x);  ffma2(a1y, w1[k].y, hv.y);
        }
        float acc0 = f32x2_hsum(a0x, a0y);
        float acc1 = f32x2_hsum(a1x, a1y);
#pragma unroll
        for (int o = 16; o > 0; o >>= 1) {
            acc0 += __shfl_xor_sync(0xffffffffu, acc0, o);
            acc1 += __shfl_xor_sync(0xffffffffu, acc1, o);
        }

        float h0n = 0.f, h1n = 0.f;
        if (lane == 0) {
            h0n = tanh_fast(a0 + acc0);
            h1n = tanh_fast(a1 + acc1);
            c_s[wid * 2 + 0] = h0n;     // smem collect only — no global stores
            c_s[wid * 2 + 1] = h1n;     // queued ahead of the publish
        }
        __syncthreads();   // bar B: c_s complete; all h_s reads done before reuse

        // Publish FIRST, from warp 7 (highest arbiter priority): its 4 STGs
        // enter the LSU queue ahead of other warps' poll/out traffic.
        if (wid == 7 && lane < 4)
            stg_vol_v4(hn + cta * 4 + lane, *(const float4*)&c_s[lane * 4]);

        // Residual outputs AFTER the publish point (values live in registers).
        if (lane == 0) {
            out[(size_t)t * DIMS + row0] = xr0 + h0n;
            out[(size_t)t * DIMS + row1] = xr1 + h1n;
        }
    }
}

// ---------------- launch -------------------------------------------------------
extern "C" void kernel_launch(void* const* d_in, const int* in_sizes, int n_in,
                              void* d_out, int out_size) {
    const float* X    = (const float*)d_in[0];  // [SEQ, DIMS]
    const float* W_hi = (const float*)d_in[1];  // [DIMS, DIMS]
    const float* W_hh = (const float*)d_in[2];  // [DIMS, DIMS]
    const float* b    = (const float*)d_in[3];  // [DIMS]
    const float* h0   = (const float*)d_in[4];  // [DIMS]
    float* out = (float*)d_out;

    float* A;
    cudaGetSymbolAddress((void**)&A, g_A);

    poison_kernel<<<1024, 256>>>();
    seed_kernel<<<(DIMS + 255) / 256, 256>>>(h0);

    dim3 ggrid(DIMS / BN, SEQ / BM);            // (16, 32)
    gemm_kernel<<<ggrid, 256>>>(X, W_hi, b, A);

    rnn_kernel<<<NCTA, RNN_THREADS>>>(X, W_hh, out);
}

// round 11
// speedup vs baseline: 1.1124x; 1.1124x over previous
#include <cuda_runtime.h>

#define DIMS 2048
#define SEQ  4096
#define SENT 2.0f   // sentinel: tanh output is in (-1,1), h0 = 0 -> never 2.0

// ---------------- scratch (static device globals; no allocation) ------------
__device__ float g_A[SEQ * DIMS];                         // A = X @ W_hi^T + b
__device__ __align__(16) float g_hist[(SEQ + 1) * DIMS];  // write-once h history

// ---------------- small asm helpers -----------------------------------------
__device__ __forceinline__ float tanh_fast(float x) {
    float y;
    asm("tanh.approx.f32 %0, %1;" : "=f"(y) : "f"(x));
    return y;
}
__device__ __forceinline__ float4 ldg_vol_v4(const float4* p) {
    float4 v;
    asm volatile("ld.volatile.global.v4.f32 {%0,%1,%2,%3}, [%4];"
                 : "=f"(v.x), "=f"(v.y), "=f"(v.z), "=f"(v.w) : "l"(p));
    return v;
}
__device__ __forceinline__ void stg_vol_v4(float4* p, float4 v) {
    asm volatile("st.volatile.global.v4.f32 [%0], {%1,%2,%3,%4};"
                 :: "l"(p), "f"(v.x), "f"(v.y), "f"(v.z), "f"(v.w) : "memory");
}
// packed fp32x2 ops
__device__ __forceinline__ void ffma2(unsigned long long& d,
                                      unsigned long long a, unsigned long long b) {
    asm("fma.rn.f32x2 %0, %1, %2, %0;" : "+l"(d) : "l"(a), "l"(b));
}
__device__ __forceinline__ unsigned long long add2(unsigned long long a,
                                                   unsigned long long b) {
    unsigned long long s;
    asm("add.rn.f32x2 %0, %1, %2;" : "=l"(s) : "l"(a), "l"(b));
    return s;
}
__device__ __forceinline__ unsigned long long pack2(float x) {
    unsigned long long r;
    asm("mov.b64 %0, {%1, %1};" : "=l"(r) : "f"(x));
    return r;
}
__device__ __forceinline__ float f32x2_hsum(unsigned long long a, unsigned long long b) {
    unsigned long long s = add2(a, b);
    float2 f = *reinterpret_cast<float2*>(&s);
    return f.x + f.y;
}

// ---------------- init: poison history, seed h0 -------------------------------
__global__ void poison_kernel() {
    const float4 s = make_float4(SENT, SENT, SENT, SENT);
    float4* p = (float4*)g_hist;
    const int total = (SEQ + 1) * (DIMS / 4);
    for (int w = blockIdx.x * blockDim.x + threadIdx.x; w < total;
         w += gridDim.x * blockDim.x)
        p[w] = s;
}
__global__ void seed_kernel(const float* __restrict__ h0) {
    int i = blockIdx.x * blockDim.x + threadIdx.x;
    if (i < DIMS) g_hist[i] = h0[i];
}

// ---------------- phase 1: A = X @ W^T + b  (packed f32x2 GEMM, champion) -----
#define BM 128
#define BN 128
#define BK 8

__global__ __launch_bounds__(256) void gemm_kernel(
    const float* __restrict__ X, const float* __restrict__ W,
    const float* __restrict__ b, float* __restrict__ A)
{
    __shared__ __align__(16) float Xs[BK][BM];
    __shared__ __align__(16) float Ws[BK][BN];

    const int tid = threadIdx.x;
    const int m0  = blockIdx.y * BM;
    const int n0  = blockIdx.x * BN;
    const int tx  = tid & 15;
    const int ty  = tid >> 4;
    const int lr  = tid >> 1;
    const int lk  = (tid & 1) * 4;

    unsigned long long acc[8][4];
#pragma unroll
    for (int i = 0; i < 8; i++)
#pragma unroll
        for (int jp = 0; jp < 4; jp++) acc[i][jp] = 0ull;

    for (int k0 = 0; k0 < DIMS; k0 += BK) {
        float4 xv = *(const float4*)(X + (size_t)(m0 + lr) * DIMS + k0 + lk);
        float4 wv = *(const float4*)(W + (size_t)(n0 + lr) * DIMS + k0 + lk);
        __syncthreads();
        Xs[lk + 0][lr] = xv.x; Xs[lk + 1][lr] = xv.y;
        Xs[lk + 2][lr] = xv.z; Xs[lk + 3][lr] = xv.w;
        Ws[lk + 0][lr] = wv.x; Ws[lk + 1][lr] = wv.y;
        Ws[lk + 2][lr] = wv.z; Ws[lk + 3][lr] = wv.w;
        __syncthreads();
#pragma unroll
        for (int k = 0; k < BK; k++) {
            unsigned long long xd[8], wp[4];
#pragma unroll
            for (int i = 0; i < 8; i++) xd[i] = pack2(Xs[k][ty + 16 * i]);
#pragma unroll
            for (int jp = 0; jp < 4; jp++)
                wp[jp] = *(const unsigned long long*)&Ws[k][tx * 2 + 32 * jp];
#pragma unroll
            for (int i = 0; i < 8; i++)
#pragma unroll
                for (int jp = 0; jp < 4; jp++) ffma2(acc[i][jp], xd[i], wp[jp]);
        }
    }
    unsigned long long bp[4];
#pragma unroll
    for (int jp = 0; jp < 4; jp++)
        bp[jp] = *(const unsigned long long*)&b[n0 + tx * 2 + 32 * jp];
#pragma unroll
    for (int i = 0; i < 8; i++) {
        const int m = m0 + ty + 16 * i;
#pragma unroll
        for (int jp = 0; jp < 4; jp++) {
            *(unsigned long long*)&A[(size_t)m * DIMS + n0 + tx * 2 + 32 * jp] =
                add2(acc[i][jp], bp[jp]);
        }
    }
}

// ---------------- phase 2: persistent sequential RNN --------------------------
// Exchange protocol: EXACT champion (R5). Compute between the bars is
// restructured as k-split-2: warp w = row-group (w&3, 4 rows) x k-half (w>>2).
// Each warp reads only its 4KB k-half of h -> smem crossbar traffic halves
// (64KB -> 32KB per step). Partials combined through an 8x16B smem exchange.
#define NCTA 128
#define RPC  16
#define RNN_THREADS 256

__global__ __launch_bounds__(RNN_THREADS, 1) void rnn_kernel(
    const float* __restrict__ X, const float* __restrict__ Whh,
    float* __restrict__ out)
{
    __shared__ __align__(16) float4 h_s[DIMS / 4];  // 8 KB staging
    __shared__ __align__(16) float4 part_s[8];      // per-warp row-group partials
    __shared__ __align__(16) float4 c_s4[4];        // final 16 h (as 4 sectors)

    const int tid  = threadIdx.x;
    const int wid  = tid >> 5;
    const int lane = tid & 31;
    const int cta  = blockIdx.x;
    const int kh   = wid >> 2;              // k-half: 0 or 1
    const int rg   = wid & 3;               // row group: 0..3
    const int rbase = cta * RPC + rg * 4;   // 4 consecutive rows

    // W_hh slab: 4 rows x this k-half, packed f32x2 pairs. 128 regs.
    ulonglong2 w[4][8];
#pragma unroll
    for (int r = 0; r < 4; r++) {
        const ulonglong2* Wr =
            (const ulonglong2*)(Whh + (size_t)(rbase + r) * DIMS) + kh * 256;
#pragma unroll
        for (int i = 0; i < 8; i++) w[r][i] = Wr[lane + 32 * i];
    }

    for (int t = 0; t < SEQ; t++) {
        const float4* hb = (const float4*)(g_hist + (size_t)t * DIMS);
        float4*       hn = (float4*)(g_hist + (size_t)(t + 1) * DIMS);

        // Step-constant operands (warps 0-3 lane0 own the final combine).
        float4 a4 = make_float4(0.f, 0.f, 0.f, 0.f);
        float4 x4 = make_float4(0.f, 0.f, 0.f, 0.f);
        if (wid < 4 && lane == 0) {
            a4 = *(const float4*)(g_A + (size_t)t * DIMS + rbase);
            x4 = *(const float4*)(X   + (size_t)t * DIMS + rbase);
        }

        // ===== EXCHANGE INGEST: byte-identical to champion =====
        {
            float4 va = ldg_vol_v4(hb + tid);
            float4 vb = ldg_vol_v4(hb + tid + RNN_THREADS);
            while (va.x == SENT || va.y == SENT || va.z == SENT || va.w == SENT)
                va = ldg_vol_v4(hb + tid);
            while (vb.x == SENT || vb.y == SENT || vb.z == SENT || vb.w == SENT)
                vb = ldg_vol_v4(hb + tid + RNN_THREADS);
            h_s[tid]               = va;
            h_s[tid + RNN_THREADS] = vb;
        }
        __syncthreads();   // bar A: h_s fully staged

        // ===== COMPUTE: 4 rows x k-half per warp =====
        const ulonglong2* hp = (const ulonglong2*)h_s + kh * 256;
        unsigned long long ax[4], ay[4];
#pragma unroll
        for (int r = 0; r < 4; r++) { ax[r] = 0ull; ay[r] = 0ull; }
#pragma unroll
        for (int i = 0; i < 8; i++) {
            ulonglong2 hv = hp[lane + 32 * i];
#pragma unroll
            for (int r = 0; r < 4; r++) {
                ffma2(ax[r], w[r][i].x, hv.x);
                ffma2(ay[r], w[r][i].y, hv.y);
            }
        }
        float s0 = f32x2_hsum(ax[0], ay[0]);
        float s1 = f32x2_hsum(ax[1], ay[1]);
        float s2 = f32x2_hsum(ax[2], ay[2]);
        float s3 = f32x2_hsum(ax[3], ay[3]);
#pragma unroll
        for (int o = 16; o > 0; o >>= 1) {
            s0 += __shfl_xor_sync(0xffffffffu, s0, o);
            s1 += __shfl_xor_sync(0xffffffffu, s1, o);
            s2 += __shfl_xor_sync(0xffffffffu, s2, o);
            s3 += __shfl_xor_sync(0xffffffffu, s3, o);
        }
        if (lane == 0) part_s[wid] = make_float4(s0, s1, s2, s3);
        __syncthreads();   // bar P: partials visible

        // Combine halves, tanh, collect, residual out (warps 0-3 lane0).
        if (wid < 4 && lane == 0) {
            float4 pa = part_s[wid];
            float4 pb = part_s[wid + 4];
            float h0 = tanh_fast(a4.x + pa.x + pb.x);
            float h1 = tanh_fast(a4.y + pa.y + pb.y);
            float h2 = tanh_fast(a4.z + pa.z + pb.z);
            float h3 = tanh_fast(a4.w + pa.w + pb.w);
            c_s4[wid] = make_float4(h0, h1, h2, h3);
            *(float4*)(out + (size_t)t * DIMS + rbase) =
                make_float4(x4.x + h0, x4.y + h1, x4.z + h2, x4.w + h3);
        }
        __syncthreads();   // bar B: c_s4 complete; all h_s reads done

        // ===== PUBLISH: byte-identical to champion (tid<4, full sectors) =====
        if (tid < 4) stg_vol_v4(hn + cta * 4 + tid, c_s4[tid]);
    }
}

// ---------------- launch -------------------------------------------------------
extern "C" void kernel_launch(void* const* d_in, const int* in_sizes, int n_in,
                              void* d_out, int out_size) {
    const float* X    = (const float*)d_in[0];  // [SEQ, DIMS]
    const float* W_hi = (const float*)d_in[1];  // [DIMS, DIMS]
    const float* W_hh = (const float*)d_in[2];  // [DIMS, DIMS]
    const float* b    = (const float*)d_in[3];  // [DIMS]
    const float* h0   = (const float*)d_in[4];  // [DIMS]
    float* out = (float*)d_out;

    float* A;
    cudaGetSymbolAddress((void**)&A, g_A);

    poison_kernel<<<1024, 256>>>();
    seed_kernel<<<(DIMS + 255) / 256, 256>>>(h0);

    dim3 ggrid(DIMS / BN, SEQ / BM);            // (16, 32)
    gemm_kernel<<<ggrid, 256>>>(X, W_hi, b, A);

    rnn_kernel<<<NCTA, RNN_THREADS>>>(X, W_hh, out);
}